// round 1
// baseline (speedup 1.0000x reference)
#include <cuda_runtime.h>
#include <math.h>

// Problem constants
#define Bx  2
#define Sx  4096
#define Dx  512
#define Hx  8
#define DKx 64
#define SWx 128   // Sx/32 mask words per row

// Scratch (no cudaMalloc allowed) — ~71 MB total
__device__ float    g_Qp[Bx * Sx * Dx];
__device__ float    g_Kp[Bx * Sx * Dx];
__device__ float    g_Vp[Bx * Sx * Dx];
__device__ float    g_AO[Bx * Sx * Dx];
__device__ unsigned g_mb[Bx * Sx * SWx];

// ---------------------------------------------------------------------------
// 1) mask (int32 [B,S,S]) -> bitmask (1 bit per entry). One coalesced pass.
// ---------------------------------------------------------------------------
__global__ void mask_bits_kernel(const int* __restrict__ mask) {
    int idx = blockIdx.x * 256 + threadIdx.x;
    int m = mask[idx];
    unsigned w = __ballot_sync(0xffffffffu, m != 0);
    if ((threadIdx.x & 31) == 0) g_mb[idx >> 5] = w;
}

// ---------------------------------------------------------------------------
// 2) SGEMM: C[M,N] = A[M,K] @ W[K,N], all row-major fp32.
//    64x64 CTA tile, BK=16, 256 threads, 4x4 register micro-tile.
// ---------------------------------------------------------------------------
__global__ __launch_bounds__(256) void sgemm64(
    const float* __restrict__ A, const float* __restrict__ W,
    float* __restrict__ C, int M, int N, int K)
{
    __shared__ __align__(16) float As[16][68];  // [k][m] (transposed stage)
    __shared__ __align__(16) float Ws[16][68];  // [k][n]

    const int tid = threadIdx.x;
    const int tx = tid & 15, ty = tid >> 4;
    const int m0 = blockIdx.y << 6, n0 = blockIdx.x << 6;

    const int arow = tid >> 2;         // 0..63
    const int ak   = (tid & 3) << 2;   // 0,4,8,12
    const int wrow = tid >> 4;         // 0..15
    const int wn   = (tid & 15) << 2;  // 0..60

    float acc[4][4] = {};

    for (int k0 = 0; k0 < K; k0 += 16) {
        float4 a4 = *(const float4*)(A + (size_t)(m0 + arow) * K + k0 + ak);
        float4 w4 = *(const float4*)(W + (size_t)(k0 + wrow) * N + n0 + wn);
        __syncthreads();
        As[ak + 0][arow] = a4.x;
        As[ak + 1][arow] = a4.y;
        As[ak + 2][arow] = a4.z;
        As[ak + 3][arow] = a4.w;
        *(float4*)&Ws[wrow][wn] = w4;
        __syncthreads();
#pragma unroll
        for (int kk = 0; kk < 16; kk++) {
            float4 av = *(const float4*)&As[kk][ty << 2];
            float4 wv = *(const float4*)&Ws[kk][tx << 2];
            acc[0][0] += av.x * wv.x; acc[0][1] += av.x * wv.y;
            acc[0][2] += av.x * wv.z; acc[0][3] += av.x * wv.w;
            acc[1][0] += av.y * wv.x; acc[1][1] += av.y * wv.y;
            acc[1][2] += av.y * wv.z; acc[1][3] += av.y * wv.w;
            acc[2][0] += av.z * wv.x; acc[2][1] += av.z * wv.y;
            acc[2][2] += av.z * wv.z; acc[2][3] += av.z * wv.w;
            acc[3][0] += av.w * wv.x; acc[3][1] += av.w * wv.y;
            acc[3][2] += av.w * wv.z; acc[3][3] += av.w * wv.w;
        }
    }
#pragma unroll
    for (int i = 0; i < 4; i++) {
        *(float4*)(C + (size_t)(m0 + (ty << 2) + i) * N + n0 + (tx << 2)) =
            make_float4(acc[i][0], acc[i][1], acc[i][2], acc[i][3]);
    }
}

// ---------------------------------------------------------------------------
// 3) Flash-style attention. One CTA = (b, h, 64 q rows). 64-wide k tiles.
//    Online softmax, exact -1e9 masking semantics of the reference.
// ---------------------------------------------------------------------------
#define TS 68  // smem row stride (floats)

__global__ __launch_bounds__(256) void attn_kernel() {
    extern __shared__ __align__(16) float sm[];
    float* Qst = sm;                 // [d][r]  64x68
    float* Kst = sm + 64 * TS;       // [d][c]
    float* Vs  = sm + 2 * 64 * TS;   // [c][d]
    float* Pst = sm + 3 * 64 * TS;   // [c][r]

    const int tid = threadIdx.x;
    const int tx = tid & 15, ty = tid >> 4;
    const int q0 = blockIdx.x << 6;
    const int h = blockIdx.y, b = blockIdx.z;

    const size_t baseQ  = ((size_t)b * Sx + q0) * Dx + (size_t)h * DKx;
    const size_t baseKV = (size_t)b * Sx * Dx + (size_t)h * DKx;

    // Load Q tile, stored transposed Qst[d][r]
#pragma unroll
    for (int u = 0; u < 4; u++) {
        int f = tid + u * 256;
        int row = f >> 4;
        int cv = (f & 15) << 2;
        float4 q4 = *(const float4*)(g_Qp + baseQ + (size_t)row * Dx + cv);
        Qst[(cv + 0) * TS + row] = q4.x;
        Qst[(cv + 1) * TS + row] = q4.y;
        Qst[(cv + 2) * TS + row] = q4.z;
        Qst[(cv + 3) * TS + row] = q4.w;
    }

    float mrow[4] = {-INFINITY, -INFINITY, -INFINITY, -INFINITY};
    float lrow[4] = {0.f, 0.f, 0.f, 0.f};
    float acc[4][4] = {};

    const int bsh = (tx << 2) & 31;          // bit shift within mask word
    const size_t mbase = ((size_t)b * Sx + q0 + (ty << 2)) * SWx;

    for (int kt = 0; kt < Sx; kt += 64) {
        __syncthreads();  // previous PV done before overwriting K/V/P
        // Load K (transposed) and V tiles
#pragma unroll
        for (int u = 0; u < 4; u++) {
            int f = tid + u * 256;
            int row = f >> 4;
            int cv = (f & 15) << 2;
            size_t g = baseKV + (size_t)(kt + row) * Dx + cv;
            float4 k4 = *(const float4*)(g_Kp + g);
            Kst[(cv + 0) * TS + row] = k4.x;
            Kst[(cv + 1) * TS + row] = k4.y;
            Kst[(cv + 2) * TS + row] = k4.z;
            Kst[(cv + 3) * TS + row] = k4.w;
            float4 v4 = *(const float4*)(g_Vp + g);
            *(float4*)&Vs[row * TS + cv] = v4;
        }
        __syncthreads();

        // Scores S = Q @ K^T (4x4 per thread)
        float s[4][4] = {};
#pragma unroll 16
        for (int d = 0; d < 64; d++) {
            float4 qv = *(const float4*)&Qst[d * TS + (ty << 2)];
            float4 kv = *(const float4*)&Kst[d * TS + (tx << 2)];
            s[0][0] += qv.x * kv.x; s[0][1] += qv.x * kv.y;
            s[0][2] += qv.x * kv.z; s[0][3] += qv.x * kv.w;
            s[1][0] += qv.y * kv.x; s[1][1] += qv.y * kv.y;
            s[1][2] += qv.y * kv.z; s[1][3] += qv.y * kv.w;
            s[2][0] += qv.z * kv.x; s[2][1] += qv.z * kv.y;
            s[2][2] += qv.z * kv.z; s[2][3] += qv.z * kv.w;
            s[3][0] += qv.w * kv.x; s[3][1] += qv.w * kv.y;
            s[3][2] += qv.w * kv.z; s[3][3] += qv.w * kv.w;
        }

        // Scale + mask (exactly: masked -> -1e9, else s * 1/sqrt(64))
        const int wi = (kt + (tx << 2)) >> 5;
#pragma unroll
        for (int i = 0; i < 4; i++) {
            unsigned w = g_mb[mbase + (size_t)i * SWx + wi];
#pragma unroll
            for (int j = 0; j < 4; j++)
                s[i][j] = ((w >> (bsh + j)) & 1u) ? s[i][j] * 0.125f : -1e9f;
        }

        // Online softmax per row (16 lanes share a row group)
#pragma unroll
        for (int i = 0; i < 4; i++) {
            float tmax = fmaxf(fmaxf(s[i][0], s[i][1]), fmaxf(s[i][2], s[i][3]));
            tmax = fmaxf(tmax, __shfl_xor_sync(0xffffffffu, tmax, 8));
            tmax = fmaxf(tmax, __shfl_xor_sync(0xffffffffu, tmax, 4));
            tmax = fmaxf(tmax, __shfl_xor_sync(0xffffffffu, tmax, 2));
            tmax = fmaxf(tmax, __shfl_xor_sync(0xffffffffu, tmax, 1));
            float mnew = fmaxf(mrow[i], tmax);
            float corr = __expf(mrow[i] - mnew);
            float ps = 0.f;
#pragma unroll
            for (int j = 0; j < 4; j++) {
                float p = __expf(s[i][j] - mnew);
                Pst[((tx << 2) + j) * TS + (ty << 2) + i] = p;
                ps += p;
            }
            ps += __shfl_xor_sync(0xffffffffu, ps, 8);
            ps += __shfl_xor_sync(0xffffffffu, ps, 4);
            ps += __shfl_xor_sync(0xffffffffu, ps, 2);
            ps += __shfl_xor_sync(0xffffffffu, ps, 1);
            lrow[i] = lrow[i] * corr + ps;
            mrow[i] = mnew;
            acc[i][0] *= corr; acc[i][1] *= corr;
            acc[i][2] *= corr; acc[i][3] *= corr;
        }
        __syncthreads();  // all of P written

        // O += P @ V
#pragma unroll 16
        for (int jj = 0; jj < 64; jj++) {
            float4 pv = *(const float4*)&Pst[jj * TS + (ty << 2)];
            float4 vv = *(const float4*)&Vs[jj * TS + (tx << 2)];
            acc[0][0] += pv.x * vv.x; acc[0][1] += pv.x * vv.y;
            acc[0][2] += pv.x * vv.z; acc[0][3] += pv.x * vv.w;
            acc[1][0] += pv.y * vv.x; acc[1][1] += pv.y * vv.y;
            acc[1][2] += pv.y * vv.z; acc[1][3] += pv.y * vv.w;
            acc[2][0] += pv.z * vv.x; acc[2][1] += pv.z * vv.y;
            acc[2][2] += pv.z * vv.z; acc[2][3] += pv.z * vv.w;
            acc[3][0] += pv.w * vv.x; acc[3][1] += pv.w * vv.y;
            acc[3][2] += pv.w * vv.z; acc[3][3] += pv.w * vv.w;
        }
    }

    // Normalize and store [B,S,D] layout
#pragma unroll
    for (int i = 0; i < 4; i++) {
        float inv = 1.0f / lrow[i];
        *(float4*)(g_AO + baseQ + (size_t)((ty << 2) + i) * Dx + (tx << 2)) =
            make_float4(acc[i][0] * inv, acc[i][1] * inv,
                        acc[i][2] * inv, acc[i][3] * inv);
    }
}

// ---------------------------------------------------------------------------
// Launch
// ---------------------------------------------------------------------------
extern "C" void kernel_launch(void* const* d_in, const int* in_sizes, int n_in,
                              void* d_out, int out_size) {
    const float* q    = (const float*)d_in[0];
    const float* k    = (const float*)d_in[1];
    const float* v    = (const float*)d_in[2];
    const int*   mask = (const int*)  d_in[3];
    const float* wq   = (const float*)d_in[4];
    const float* wk   = (const float*)d_in[5];
    const float* wv   = (const float*)d_in[6];
    const float* wo   = (const float*)d_in[7];

    float *Qp, *Kp, *Vp, *AO;
    cudaGetSymbolAddress((void**)&Qp, g_Qp);
    cudaGetSymbolAddress((void**)&Kp, g_Kp);
    cudaGetSymbolAddress((void**)&Vp, g_Vp);
    cudaGetSymbolAddress((void**)&AO, g_AO);

    // 1) mask compression
    mask_bits_kernel<<<(Bx * Sx * Sx) / 256, 256>>>(mask);

    // 2) projections
    dim3 gg(Dx / 64, (Bx * Sx) / 64);
    sgemm64<<<gg, 256>>>(q, wq, Qp, Bx * Sx, Dx, Dx);
    sgemm64<<<gg, 256>>>(k, wk, Kp, Bx * Sx, Dx, Dx);
    sgemm64<<<gg, 256>>>(v, wv, Vp, Bx * Sx, Dx, Dx);

    // 3) attention
    const int smem_bytes = 4 * 64 * TS * (int)sizeof(float);  // 69632
    cudaFuncSetAttribute(attn_kernel,
                         cudaFuncAttributeMaxDynamicSharedMemorySize, smem_bytes);
    attn_kernel<<<dim3(Sx / 64, Hx, Bx), 256, smem_bytes>>>();

    // 4) output projection -> d_out
    sgemm64<<<gg, 256>>>(AO, wo, (float*)d_out, Bx * Sx, Dx, Dx);
}

// round 2
// speedup vs baseline: 2.1748x; 2.1748x over previous
#include <cuda_runtime.h>
#include <math.h>

// Problem constants
#define Bx  2
#define Sx  4096
#define Dx  512
#define Hx  8
#define DKx 64
#define SWx 128   // Sx/32 mask words per row
#define PD  68    // smem row stride (floats): g*68+t = g*4+t mod 32 -> conflict-free frags

// Scratch (no cudaMalloc allowed)
__device__ float    g_Qp[Bx * Sx * Dx];
__device__ float    g_Kp[Bx * Sx * Dx];
__device__ float    g_Vp[Bx * Sx * Dx];
__device__ float    g_AO[Bx * Sx * Dx];
__device__ unsigned g_mb[Bx * Sx * SWx];

// ---------------------------------------------------------------------------
// Helpers: tf32 round + warp MMA m16n8k8 (row.col, f32 accum)
// ---------------------------------------------------------------------------
__device__ __forceinline__ float tf32r(float x) {
    unsigned u;
    asm("cvt.rna.tf32.f32 %0, %1;" : "=r"(u) : "f"(x));
    return __uint_as_float(u);
}
__device__ __forceinline__ void mma8(float* c, unsigned a0, unsigned a1,
                                     unsigned a2, unsigned a3,
                                     unsigned b0, unsigned b1) {
    asm volatile(
        "mma.sync.aligned.m16n8k8.row.col.f32.tf32.tf32.f32 "
        "{%0,%1,%2,%3}, {%4,%5,%6,%7}, {%8,%9}, {%0,%1,%2,%3};\n"
        : "+f"(c[0]), "+f"(c[1]), "+f"(c[2]), "+f"(c[3])
        : "r"(a0), "r"(a1), "r"(a2), "r"(a3), "r"(b0), "r"(b1));
}
#define ASU(x) __float_as_uint(x)

// ---------------------------------------------------------------------------
// 1) mask (int32 [B,S,S]) -> bitmask. One coalesced pass.
// ---------------------------------------------------------------------------
__global__ void mask_bits_kernel(const int* __restrict__ mask) {
    int idx = blockIdx.x * 256 + threadIdx.x;
    int m = mask[idx];
    unsigned w = __ballot_sync(0xffffffffu, m != 0);
    if ((threadIdx.x & 31) == 0) g_mb[idx >> 5] = w;
}

// ---------------------------------------------------------------------------
// 2) tf32 MMA GEMM: C[M,N] = A[M,K] @ W[K,N], row-major fp32 in/out.
//    CTA tile 64x64, 4 warps (16 rows x 64 cols each), K-chunk 64.
// ---------------------------------------------------------------------------
__global__ __launch_bounds__(128) void gemm_mma(
    const float* __restrict__ A, const float* __restrict__ W,
    float* __restrict__ C, int M, int N, int K)
{
    __shared__ __align__(16) float As[64 * PD];  // [m][k]
    __shared__ __align__(16) float Ws[64 * PD];  // [n][k] (transposed stage)

    const int tid = threadIdx.x, warp = tid >> 5, lane = tid & 31;
    const int g = lane >> 2, t = lane & 3;
    const int m0 = blockIdx.y << 6, n0 = blockIdx.x << 6;
    const int rw = warp << 4;

    float acc[8][4] = {};

    for (int k0 = 0; k0 < K; k0 += 64) {
        __syncthreads();
#pragma unroll
        for (int u = 0; u < 8; u++) {
            int f = tid + (u << 7);
            int r = f >> 4, kv = (f & 15) << 2;
            float4 a4 = *(const float4*)(A + (size_t)(m0 + r) * K + k0 + kv);
            float4 c4 = make_float4(tf32r(a4.x), tf32r(a4.y), tf32r(a4.z), tf32r(a4.w));
            *(float4*)&As[r * PD + kv] = c4;

            int kk = f >> 4, nv = (f & 15) << 2;
            float4 w4 = *(const float4*)(W + (size_t)(k0 + kk) * N + n0 + nv);
            Ws[(nv + 0) * PD + kk] = tf32r(w4.x);
            Ws[(nv + 1) * PD + kk] = tf32r(w4.y);
            Ws[(nv + 2) * PD + kk] = tf32r(w4.z);
            Ws[(nv + 3) * PD + kk] = tf32r(w4.w);
        }
        __syncthreads();
#pragma unroll
        for (int ks = 0; ks < 8; ks++) {
            unsigned a0 = ASU(As[(rw + g)     * PD + (ks << 3) + t]);
            unsigned a1 = ASU(As[(rw + g + 8) * PD + (ks << 3) + t]);
            unsigned a2 = ASU(As[(rw + g)     * PD + (ks << 3) + t + 4]);
            unsigned a3 = ASU(As[(rw + g + 8) * PD + (ks << 3) + t + 4]);
#pragma unroll
            for (int nt = 0; nt < 8; nt++) {
                unsigned b0 = ASU(Ws[((nt << 3) + g) * PD + (ks << 3) + t]);
                unsigned b1 = ASU(Ws[((nt << 3) + g) * PD + (ks << 3) + t + 4]);
                mma8(acc[nt], a0, a1, a2, a3, b0, b1);
            }
        }
    }
#pragma unroll
    for (int nt = 0; nt < 8; nt++) {
        int c0 = (nt << 3) + 2 * t;
        *(float2*)(C + (size_t)(m0 + rw + g)     * N + n0 + c0) =
            make_float2(acc[nt][0], acc[nt][1]);
        *(float2*)(C + (size_t)(m0 + rw + g + 8) * N + n0 + c0) =
            make_float2(acc[nt][2], acc[nt][3]);
    }
}

// ---------------------------------------------------------------------------
// 3) Flash attention, tf32 MMA. CTA = (b, h, 64 q rows), 4 warps.
//    Warp owns 16 full score rows -> softmax reduces only across the
//    4-lane group (shfl_xor 1,2). P restaged through smem per-warp.
// ---------------------------------------------------------------------------
__global__ __launch_bounds__(128) void attn_mma() {
    extern __shared__ __align__(16) float sm[];
    float* Qs = sm;              // [r][d]
    float* Ks = sm + 64 * PD;    // [c][d]
    float* Vt = sm + 2 * 64 * PD;// [d][s] (transposed)
    float* Ps = sm + 3 * 64 * PD;// [r][s]

    const int tid = threadIdx.x, warp = tid >> 5, lane = tid & 31;
    const int g = lane >> 2, t = lane & 3;
    const int q0 = blockIdx.x << 6, h = blockIdx.y, b = blockIdx.z;
    const int rw = warp << 4;
    const size_t baseQ  = ((size_t)b * Sx + q0) * Dx + (size_t)h * DKx;
    const size_t baseKV = (size_t)b * Sx * Dx + (size_t)h * DKx;

    // Stage Q (tf32)
#pragma unroll
    for (int u = 0; u < 8; u++) {
        int f = tid + (u << 7);
        int r = f >> 4, dv = (f & 15) << 2;
        float4 q4 = *(const float4*)(g_Qp + baseQ + (size_t)r * Dx + dv);
        *(float4*)&Qs[r * PD + dv] =
            make_float4(tf32r(q4.x), tf32r(q4.y), tf32r(q4.z), tf32r(q4.w));
    }

    float o[8][4] = {};
    float mr0 = -INFINITY, mr1 = -INFINITY, l0 = 0.f, l1 = 0.f;
    const int row0 = q0 + rw + g;
    const size_t mb0 = ((size_t)b * Sx + row0) * SWx;
    const size_t mb1 = mb0 + (size_t)8 * SWx;

    for (int kt = 0; kt < Sx; kt += 64) {
        __syncthreads();  // all warps done with previous K/V tiles
#pragma unroll
        for (int u = 0; u < 8; u++) {
            int f = tid + (u << 7);
            int r = f >> 4, dv = (f & 15) << 2;
            size_t gofs = baseKV + (size_t)(kt + r) * Dx + dv;
            float4 k4 = *(const float4*)(g_Kp + gofs);
            *(float4*)&Ks[r * PD + dv] =
                make_float4(tf32r(k4.x), tf32r(k4.y), tf32r(k4.z), tf32r(k4.w));
            float4 v4 = *(const float4*)(g_Vp + gofs);
            Vt[(dv + 0) * PD + r] = tf32r(v4.x);
            Vt[(dv + 1) * PD + r] = tf32r(v4.y);
            Vt[(dv + 2) * PD + r] = tf32r(v4.z);
            Vt[(dv + 3) * PD + r] = tf32r(v4.w);
        }
        __syncthreads();

        // S = Q @ K^T
        float sa[8][4] = {};
#pragma unroll
        for (int ks = 0; ks < 8; ks++) {
            unsigned a0 = ASU(Qs[(rw + g)     * PD + (ks << 3) + t]);
            unsigned a1 = ASU(Qs[(rw + g + 8) * PD + (ks << 3) + t]);
            unsigned a2 = ASU(Qs[(rw + g)     * PD + (ks << 3) + t + 4]);
            unsigned a3 = ASU(Qs[(rw + g + 8) * PD + (ks << 3) + t + 4]);
#pragma unroll
            for (int nt = 0; nt < 8; nt++) {
                unsigned b0 = ASU(Ks[((nt << 3) + g) * PD + (ks << 3) + t]);
                unsigned b1 = ASU(Ks[((nt << 3) + g) * PD + (ks << 3) + t + 4]);
                mma8(sa[nt], a0, a1, a2, a3, b0, b1);
            }
        }

        // Scale + mask: masked -> -1e9 (exact reference semantics)
        const int wi = kt >> 5;
        unsigned m00 = g_mb[mb0 + wi], m01 = g_mb[mb0 + wi + 1];
        unsigned m10 = g_mb[mb1 + wi], m11 = g_mb[mb1 + wi + 1];
#pragma unroll
        for (int nt = 0; nt < 8; nt++) {
            int c0 = (nt << 3) + 2 * t;
            unsigned wr0 = (c0 < 32) ? m00 : m01;
            unsigned wr1 = (c0 < 32) ? m10 : m11;
            int bit = c0 & 31;
            sa[nt][0] = ((wr0 >> bit) & 1u)       ? sa[nt][0] * 0.125f : -1e9f;
            sa[nt][1] = ((wr0 >> (bit + 1)) & 1u) ? sa[nt][1] * 0.125f : -1e9f;
            sa[nt][2] = ((wr1 >> bit) & 1u)       ? sa[nt][2] * 0.125f : -1e9f;
            sa[nt][3] = ((wr1 >> (bit + 1)) & 1u) ? sa[nt][3] * 0.125f : -1e9f;
        }

        // Online softmax (rows g and g+8 of this warp's 16)
        float t0 = -INFINITY, t1 = -INFINITY;
#pragma unroll
        for (int nt = 0; nt < 8; nt++) {
            t0 = fmaxf(t0, fmaxf(sa[nt][0], sa[nt][1]));
            t1 = fmaxf(t1, fmaxf(sa[nt][2], sa[nt][3]));
        }
        t0 = fmaxf(t0, __shfl_xor_sync(0xffffffffu, t0, 1));
        t0 = fmaxf(t0, __shfl_xor_sync(0xffffffffu, t0, 2));
        t1 = fmaxf(t1, __shfl_xor_sync(0xffffffffu, t1, 1));
        t1 = fmaxf(t1, __shfl_xor_sync(0xffffffffu, t1, 2));
        float mn0 = fmaxf(mr0, t0), mn1 = fmaxf(mr1, t1);
        float corr0 = __expf(mr0 - mn0), corr1 = __expf(mr1 - mn1);
        float ps0 = 0.f, ps1 = 0.f;
#pragma unroll
        for (int nt = 0; nt < 8; nt++) {
            float p0 = __expf(sa[nt][0] - mn0);
            float p1 = __expf(sa[nt][1] - mn0);
            float p2 = __expf(sa[nt][2] - mn1);
            float p3 = __expf(sa[nt][3] - mn1);
            ps0 += p0 + p1; ps1 += p2 + p3;
            int c0 = (nt << 3) + 2 * t;
            *(float2*)&Ps[(rw + g)     * PD + c0] = make_float2(tf32r(p0), tf32r(p1));
            *(float2*)&Ps[(rw + g + 8) * PD + c0] = make_float2(tf32r(p2), tf32r(p3));
        }
        ps0 += __shfl_xor_sync(0xffffffffu, ps0, 1);
        ps0 += __shfl_xor_sync(0xffffffffu, ps0, 2);
        ps1 += __shfl_xor_sync(0xffffffffu, ps1, 1);
        ps1 += __shfl_xor_sync(0xffffffffu, ps1, 2);
        l0 = l0 * corr0 + ps0;
        l1 = l1 * corr1 + ps1;
        mr0 = mn0; mr1 = mn1;
#pragma unroll
        for (int nt = 0; nt < 8; nt++) {
            o[nt][0] *= corr0; o[nt][1] *= corr0;
            o[nt][2] *= corr1; o[nt][3] *= corr1;
        }
        __syncwarp();  // P rows are warp-private: warp-level fence suffices

        // O += P @ V
#pragma unroll
        for (int ks = 0; ks < 8; ks++) {
            unsigned a0 = ASU(Ps[(rw + g)     * PD + (ks << 3) + t]);
            unsigned a1 = ASU(Ps[(rw + g + 8) * PD + (ks << 3) + t]);
            unsigned a2 = ASU(Ps[(rw + g)     * PD + (ks << 3) + t + 4]);
            unsigned a3 = ASU(Ps[(rw + g + 8) * PD + (ks << 3) + t + 4]);
#pragma unroll
            for (int nt = 0; nt < 8; nt++) {
                unsigned b0 = ASU(Vt[((nt << 3) + g) * PD + (ks << 3) + t]);
                unsigned b1 = ASU(Vt[((nt << 3) + g) * PD + (ks << 3) + t + 4]);
                mma8(o[nt], a0, a1, a2, a3, b0, b1);
            }
        }
    }

    // Normalize + store
    float i0 = 1.f / l0, i1 = 1.f / l1;
#pragma unroll
    for (int nt = 0; nt < 8; nt++) {
        int c0 = (nt << 3) + 2 * t;
        *(float2*)(g_AO + baseQ + (size_t)(rw + g)     * Dx + c0) =
            make_float2(o[nt][0] * i0, o[nt][1] * i0);
        *(float2*)(g_AO + baseQ + (size_t)(rw + g + 8) * Dx + c0) =
            make_float2(o[nt][2] * i1, o[nt][3] * i1);
    }
}

// ---------------------------------------------------------------------------
// Launch
// ---------------------------------------------------------------------------
extern "C" void kernel_launch(void* const* d_in, const int* in_sizes, int n_in,
                              void* d_out, int out_size) {
    const float* q    = (const float*)d_in[0];
    const float* k    = (const float*)d_in[1];
    const float* v    = (const float*)d_in[2];
    const int*   mask = (const int*)  d_in[3];
    const float* wq   = (const float*)d_in[4];
    const float* wk   = (const float*)d_in[5];
    const float* wv   = (const float*)d_in[6];
    const float* wo   = (const float*)d_in[7];

    float *Qp, *Kp, *Vp, *AO;
    cudaGetSymbolAddress((void**)&Qp, g_Qp);
    cudaGetSymbolAddress((void**)&Kp, g_Kp);
    cudaGetSymbolAddress((void**)&Vp, g_Vp);
    cudaGetSymbolAddress((void**)&AO, g_AO);

    // 1) mask compression
    mask_bits_kernel<<<(Bx * Sx * Sx) / 256, 256>>>(mask);

    // 2) projections (tf32 MMA)
    dim3 gg(Dx / 64, (Bx * Sx) / 64);
    gemm_mma<<<gg, 128>>>(q, wq, Qp, Bx * Sx, Dx, Dx);
    gemm_mma<<<gg, 128>>>(k, wk, Kp, Bx * Sx, Dx, Dx);
    gemm_mma<<<gg, 128>>>(v, wv, Vp, Bx * Sx, Dx, Dx);

    // 3) attention (tf32 MMA flash)
    const int smem_bytes = 4 * 64 * PD * (int)sizeof(float);  // 69632
    cudaFuncSetAttribute(attn_mma,
                         cudaFuncAttributeMaxDynamicSharedMemorySize, smem_bytes);
    attn_mma<<<dim3(Sx / 64, Hx, Bx), 128, smem_bytes>>>();

    // 4) output projection -> d_out
    gemm_mma<<<gg, 128>>>(AO, wo, (float*)d_out, Bx * Sx, Dx, Dx);
}